// round 17
// baseline (speedup 1.0000x reference)
#include <cuda_runtime.h>
#include <math.h>

#define CC 256
#define TT 4096
#define BB 8
#define BC (BB*CC)
#define ALPHA 0.8187307530779818f
#define ONE_M_ALPHA 0.1812692469220182f
#define A8 0.20189651799465540f   /* ALPHA^8 = exp(-1.6) */

typedef unsigned long long ull;

// Packed coefficient pairs per channel: [c][m*10 + k], all already * (1-alpha)
//  k=0..3 : (e[2s], e[2s+1])    s=0..3   (even-jj tap pairs)
//  k=4    : (e[8], 0)                     (even-jj tail tap)
//  k=5    : (0, e[0])                     (odd-jj head tap)
//  k=6..9 : (e[2s+1], e[2s+2])  s=0..3   (odd-jj tap pairs)
__device__ ull   g_EP[CC][30];
__device__ float g_beP[CC][3];     // bias partials; m=0 slot includes bred

__device__ __forceinline__ ull pk2(float lo, float hi) {
    ull r; asm("mov.b64 %0, {%1, %2};" : "=l"(r) : "f"(lo), "f"(hi)); return r;
}
__device__ __forceinline__ void upk2(float& lo, float& hi, ull v) {
    asm("mov.b64 {%0, %1}, %2;" : "=f"(lo), "=f"(hi) : "l"(v));
}
__device__ __forceinline__ void fma2(ull& d, ull a, ull b) {
    asm("fma.rn.f32x2 %0, %1, %2, %0;" : "+l"(d) : "l"(a), "l"(b));
}

// ---------------- prep: 8 lanes per (c,m) pair; compile-time K; shfl-tree reduce ----------------
template<int K>
__device__ __forceinline__ void prep_accum(const float* __restrict__ w,
                                           const float* __restrict__ bb,
                                           int pc0, int sub, float wr,
                                           float (&E)[9], float& be) {
    constexpr int pad = (K - 1) / 2;
    if (sub < 6) {
        be = wr * bb[pc0 + sub];
        #pragma unroll
        for (int u = 0; u < K; u++)
            E[4 + u - pad] = wr * w[(pc0 + sub) * K + u];
    }
}

__global__ void __launch_bounds__(256) prep_kernel(
        const float* __restrict__ w3, const float* __restrict__ b3,
        const float* __restrict__ w5, const float* __restrict__ b5,
        const float* __restrict__ w9, const float* __restrict__ b9,
        const float* __restrict__ wred, const float* __restrict__ bred) {
    int tid = blockIdx.x * 256 + threadIdx.x;
    int pg  = tid >> 3;
    int sub = tid & 7;
    if (pg >= 3 * CC) return;
    int c = pg / 3;
    int m = pg - 3 * c;
    int j0 = 18 * c + 6 * m;

    float E[9];
    #pragma unroll
    for (int t = 0; t < 9; t++) E[t] = 0.f;
    float be = 0.f;
    float wr = (sub < 6) ? wred[c * 18 + 6 * m + sub] : 0.f;

    if (j0 < 6 * CC)        prep_accum<3>(w3, b3, j0,            sub, wr, E, be);
    else if (j0 < 12 * CC)  prep_accum<5>(w5, b5, j0 - 6 * CC,   sub, wr, E, be);
    else                    prep_accum<9>(w9, b9, j0 - 12 * CC,  sub, wr, E, be);

    #pragma unroll
    for (int s = 4; s > 0; s >>= 1) {
        #pragma unroll
        for (int t = 0; t < 9; t++) E[t] += __shfl_xor_sync(0xffffffffu, E[t], s);
        be += __shfl_xor_sync(0xffffffffu, be, s);
    }
    if (sub == 0) {
        #pragma unroll
        for (int t = 0; t < 9; t++) E[t] *= ONE_M_ALPHA;
        #pragma unroll
        for (int s = 0; s < 4; s++) g_EP[c][m * 10 + s] = pk2(E[2 * s], E[2 * s + 1]);
        g_EP[c][m * 10 + 4] = pk2(E[8], 0.f);
        g_EP[c][m * 10 + 5] = pk2(0.f, E[0]);
        #pragma unroll
        for (int s = 0; s < 4; s++) g_EP[c][m * 10 + 6 + s] = pk2(E[2 * s + 1], E[2 * s + 2]);
        g_beP[c][m] = be * ONE_M_ALPHA + ((m == 0) ? bred[c] * ONE_M_ALPHA : 0.f);
    }
}

// ---------------- lif: one block per (b, c); 512 threads, 8 steps/thread, PACKED f32x2 ----------------
// All data pairs are register-quad-aligned (from LDG.128); coefficient pairs pre-built by prep.
// out layout: [0,BC) pred (by k_tail), [BC,2BC) true_latency, [2BC,3BC) act.
__global__ void __launch_bounds__(512, 3) lif_kernel(const float* __restrict__ x,
                                                     const float* __restrict__ lat_scale,
                                                     float* __restrict__ out) {
    __shared__ ull sE2[30];
    __shared__ float swa[16], swb[16];
    __shared__ float s_scale;
    __shared__ int s_first;

    int tid  = threadIdx.x;
    int lane = tid & 31;
    int wrp  = tid >> 5;
    int bc = blockIdx.x;
    int b  = bc >> 8;
    int c  = bc & 255;

    if (tid < 30) sE2[tid] = g_EP[c][tid];
    if (tid == 30) s_first = TT;
    if (tid == 31) s_scale = fmaxf(lat_scale[0], 0.001f);
    __syncthreads();

    // packed accumulators: UE[p] -> u[2p] (lo=even-tap part, hi=odd? no: lo+hi = partial sums)
    ull UE[4], UO[4];
    #pragma unroll
    for (int p = 0; p < 4; p++) { UE[p] = 0ull; UO[p] = 0ull; }

    const float4 z4 = make_float4(0.f, 0.f, 0.f, 0.f);
    #pragma unroll
    for (int m = 0; m < 3; m++) {
        int xch = (3 * c + m) & 255;
        const float4* row4 = (const float4*)(x + ((size_t)(b * CC + xch)) * TT);
        float4 c0 = row4[tid * 2 + 0];
        float4 c1 = row4[tid * 2 + 1];
        float4 hp = (tid > 0)   ? row4[tid * 2 - 1] : z4;
        float4 hn = (tid < 511) ? row4[tid * 2 + 2] : z4;

        // window pairs P[k] = (w[2k], w[2k+1]) — register-aligned from the float4s
        ull P[8];
        P[0] = pk2(hp.x, hp.y); P[1] = pk2(hp.z, hp.w);
        P[2] = pk2(c0.x, c0.y); P[3] = pk2(c0.z, c0.w);
        P[4] = pk2(c1.x, c1.y); P[5] = pk2(c1.z, c1.w);
        P[6] = pk2(hn.x, hn.y); P[7] = pk2(hn.z, hn.w);

        ull e0 = sE2[m * 10 + 0], e1 = sE2[m * 10 + 1], e2 = sE2[m * 10 + 2],
            e3 = sE2[m * 10 + 3], e4 = sE2[m * 10 + 4], e5 = sE2[m * 10 + 5],
            e6 = sE2[m * 10 + 6], e7 = sE2[m * 10 + 7], e8 = sE2[m * 10 + 8],
            e9 = sE2[m * 10 + 9];

        #pragma unroll
        for (int p = 0; p < 4; p++) {
            // u[2p]: taps (0,1)(2,3)(4,5)(6,7) on P[p..p+3], tap 8 on P[p+4].lo
            fma2(UE[p], e0, P[p + 0]);
            fma2(UE[p], e1, P[p + 1]);
            fma2(UE[p], e2, P[p + 2]);
            fma2(UE[p], e3, P[p + 3]);
            fma2(UE[p], e4, P[p + 4]);
            // u[2p+1]: tap 0 on P[p].hi, taps (1,2)(3,4)(5,6)(7,8) on P[p+1..p+4]
            fma2(UO[p], e5, P[p + 0]);
            fma2(UO[p], e6, P[p + 1]);
            fma2(UO[p], e7, P[p + 2]);
            fma2(UO[p], e8, P[p + 3]);
            fma2(UO[p], e9, P[p + 4]);
        }
    }

    float u[8];
    float be = g_beP[c][0] + g_beP[c][1] + g_beP[c][2];
    #pragma unroll
    for (int p = 0; p < 4; p++) {
        float lo, hi;
        upk2(lo, hi, UE[p]);  u[2 * p]     = be + lo + hi;
        upk2(lo, hi, UO[p]);  u[2 * p + 1] = be + lo + hi;
    }

    // ---- segment transform V -> A8*V + bacc; two-level scan ----
    float bacc = 0.f;
    #pragma unroll
    for (int jj = 0; jj < 8; jj++) bacc = fmaf(ALPHA, bacc, u[jj]);

    float a = A8, bs = bacc;
    #pragma unroll
    for (int s = 1; s < 32; s <<= 1) {
        float ao = __shfl_up_sync(0xffffffffu, a, s);
        float bo = __shfl_up_sync(0xffffffffu, bs, s);
        if (lane >= s) { bs = fmaf(a, bo, bs); a *= ao; }
    }
    if (lane == 31) { swa[wrp] = a; swb[wrp] = bs; }
    __syncthreads();

    float pb = 0.f;
    for (int ww = 0; ww < wrp; ww++) pb = fmaf(swa[ww], pb, swb[ww]);

    float ae  = __shfl_up_sync(0xffffffffu, a, 1);
    float bse = __shfl_up_sync(0xffffffffu, bs, 1);
    if (lane == 0) { ae = 1.f; bse = 0.f; }
    float V = fmaf(ae, pb, bse);   // V at start of this thread's segment

    int t0 = tid * 8;
    int ft = 0x7fffffff;
    #pragma unroll
    for (int jj = 0; jj < 8; jj++) {
        V = fmaf(ALPHA, V, u[jj]);
        if (V >= 1.0f && ft == 0x7fffffff) ft = t0 + jj;
    }
    if (ft != 0x7fffffff) atomicMin(&s_first, ft);
    __syncthreads();

    if (tid == 0) {
        float tl = (float)s_first;
        out[BC + bc] = tl;
        out[2 * BC + bc] = expf(-tl / s_scale);
    }
}

// ---------------- fused tail: act -> mix -> h -> pred. 1024 threads per batch row ----------------
__global__ void __launch_bounds__(1024) k_tail(const float* __restrict__ OG,
                                               const float* __restrict__ bias,
                                               const float* __restrict__ W1,
                                               const float* __restrict__ b1,
                                               const float* __restrict__ W2,
                                               const float* __restrict__ b2,
                                               float* __restrict__ out) {
    __shared__ float4 sact4[64];
    __shared__ float smix[256];
    __shared__ float sh[128];
    __shared__ float sp[4096];

    int b = blockIdx.x;
    int t = threadIdx.x;
    int lane = t & 31;
    int wrp  = t >> 5;

    if (t < 64) sact4[t] = ((const float4*)(out + 2 * BC + b * CC))[t];
    __syncthreads();

    const float4* OG4 = (const float4*)OG;
    float4 a0 = sact4[lane];
    float4 a1 = sact4[32 + lane];
    #pragma unroll
    for (int oo = 0; oo < 8; oo++) {
        int i = wrp * 8 + oo;
        float4 g0 = OG4[i * 64 + lane];
        float4 g1 = OG4[i * 64 + 32 + lane];
        float acc = g0.x * a0.x;
        acc = fmaf(g0.y, a0.y, acc);
        acc = fmaf(g0.z, a0.z, acc);
        acc = fmaf(g0.w, a0.w, acc);
        acc = fmaf(g1.x, a1.x, acc);
        acc = fmaf(g1.y, a1.y, acc);
        acc = fmaf(g1.z, a1.z, acc);
        acc = fmaf(g1.w, a1.w, acc);
        #pragma unroll
        for (int s = 16; s > 0; s >>= 1) acc += __shfl_xor_sync(0xffffffffu, acc, s);
        if (lane == 0) smix[i] = acc + bias[i];
    }
    __syncthreads();

    {
        const float4* W14 = (const float4*)W1;
        int il = t & 31;
        int ch = t >> 5;
        float4 acc = make_float4(0.f, 0.f, 0.f, 0.f);
        #pragma unroll
        for (int jj = 0; jj < 8; jj++) {
            int j = ch * 8 + jj;
            float mj = smix[j];
            float4 wr = W14[j * 32 + il];
            acc.x = fmaf(mj, wr.x, acc.x);
            acc.y = fmaf(mj, wr.y, acc.y);
            acc.z = fmaf(mj, wr.z, acc.z);
            acc.w = fmaf(mj, wr.w, acc.w);
        }
        ((float4*)sp)[ch * 32 + il] = acc;
    }
    __syncthreads();
    if (t < 128) {
        float s = b1[t];
        #pragma unroll
        for (int ch = 0; ch < 32; ch++) s += sp[ch * 128 + t];
        sh[t] = fmaxf(s, 0.f);
    }
    __syncthreads();

    {
        const float4* W24 = (const float4*)W2;
        int il = t & 63;
        int ch = t >> 6;
        float4 acc = make_float4(0.f, 0.f, 0.f, 0.f);
        #pragma unroll
        for (int kk = 0; kk < 8; kk++) {
            int k = ch * 8 + kk;
            float hk = sh[k];
            float4 wr = W24[k * 64 + il];
            acc.x = fmaf(hk, wr.x, acc.x);
            acc.y = fmaf(hk, wr.y, acc.y);
            acc.z = fmaf(hk, wr.z, acc.z);
            acc.w = fmaf(hk, wr.w, acc.w);
        }
        ((float4*)sp)[ch * 64 + il] = acc;
    }
    __syncthreads();
    if (t < 256) {
        float r = b2[t];
        #pragma unroll
        for (int ch = 0; ch < 16; ch++) r += sp[ch * 256 + t];
        float spv = (r > 20.f) ? r : log1pf(expf(r));
        out[b * CC + t] = fminf(spv, 4096.0f);
    }
}

extern "C" void kernel_launch(void* const* d_in, const int* in_sizes, int n_in,
                              void* d_out, int out_size) {
    const float* x    = (const float*)d_in[0];
    const float* w3   = (const float*)d_in[1];
    const float* b3   = (const float*)d_in[2];
    const float* w5   = (const float*)d_in[3];
    const float* b5   = (const float*)d_in[4];
    const float* w9   = (const float*)d_in[5];
    const float* b9   = (const float*)d_in[6];
    const float* wred = (const float*)d_in[7];
    const float* bred = (const float*)d_in[8];
    const float* ls   = (const float*)d_in[9];
    const float* og   = (const float*)d_in[10];
    const float* bias = (const float*)d_in[11];
    const float* W1   = (const float*)d_in[12];
    const float* b1   = (const float*)d_in[13];
    const float* W2   = (const float*)d_in[14];
    const float* b2   = (const float*)d_in[15];
    float* out = (float*)d_out;

    prep_kernel<<<24, 256>>>(w3, b3, w5, b5, w9, b9, wred, bred);
    lif_kernel<<<BC, 512>>>(x, ls, out);
    k_tail<<<BB, 1024>>>(og, bias, W1, b1, W2, b2, out);
}